// round 14
// baseline (speedup 1.0000x reference)
#include <cuda_runtime.h>

// SparseTopKLayer: out = x + ((x*rms)*w)*mask*gamma
//   rms = rsqrt(mean(x^2)+1e-6); mask = |x_norm| >= kth_largest(|x_norm|, k)
// Rank on |x*w| (rms>0 row-constant -> identical ordering).
// One CTA per row, 256 threads, 8 elems/thread.
// Phase 1: warps compact candidates (|xw| >= lo, lo = k+160 quantile) into
//   per-warp smem segments via ballot/popc (no atomics, no histogram).
// Phase 2: warp0 alone selects the exact k-th largest among the ~400
//   candidates with a warp-local histogram loop (no block barriers).
// Fallback appends the complement when nc<k -> exact for arbitrary data.

constexpr int D    = 2048;
constexpr int T    = 256;
constexpr int BINS = 128;
constexpr int SEG  = 256;        // per-warp candidate segment (8 segs = 2048)

__device__ __forceinline__ float inv_phi_tail(float q) {
    // Phi^{-1}(1-q), q in (0,0.5]; Abramowitz-Stegun 26.2.23, |err|<4.5e-4
    q = fminf(fmaxf(q, 1e-7f), 0.4999f);
    float s = sqrtf(-2.0f * __logf(q));
    return s - (2.30753f + 0.27061f * s) / (1.0f + s * (0.99229f + 0.04481f * s));
}

__global__ void __launch_bounds__(T, 7) sparse_topk_kernel(
    const float* __restrict__ x,
    const float* __restrict__ w,
    const float* __restrict__ g,
    const int* __restrict__ kptr,
    float* __restrict__ out)
{
    const int row  = blockIdx.x;
    const int t    = threadIdx.x;
    const int lane = t & 31;
    const int wid  = t >> 5;

    __shared__ float    red[8];
    __shared__ unsigned ncw[8];
    __shared__ __align__(16) unsigned hist[BINS];
    __shared__ __align__(16) unsigned cand[D];
    __shared__ __align__(16) float xstash[D];
    __shared__ unsigned lo_sh, thr_sh;
    __shared__ int      s_sh, fb_sh;
    __shared__ float    rms_sh;

    // ---- load x (streaming), w; xw in regs; xv parked in smem; sum x^2 ----
    const float4* xr = reinterpret_cast<const float4*>(x) + (size_t)row * (D / 4);
    const float4* wv = reinterpret_cast<const float4*>(w);
    float4 xa = __ldcs(xr + t), xb = __ldcs(xr + t + T);
    float4 wa = wv[t], wb = wv[t + T];

    float xw[8];
    float ss = 0.0f;
    {
        float xv[8] = {xa.x,xa.y,xa.z,xa.w,xb.x,xb.y,xb.z,xb.w};
        float wf[8] = {wa.x,wa.y,wa.z,wa.w,wb.x,wb.y,wb.z,wb.w};
        #pragma unroll
        for (int i = 0; i < 8; i++) {
            xw[i] = xv[i] * wf[i];
            ss = fmaf(xv[i], xv[i], ss);
        }
        *reinterpret_cast<float4*>(&xstash[4 * t])       = xa;
        *reinterpret_cast<float4*>(&xstash[4 * (t + T)]) = xb;
    }
    #pragma unroll
    for (int o = 16; o > 0; o >>= 1)
        ss += __shfl_xor_sync(0xffffffffu, ss, o);
    if (lane == 0) red[wid] = ss;
    if (t == 0) fb_sh = 0;
    const int k = *kptr;
    __syncthreads();                                   // B1

    // warp0: candidate cutoff lo + round-0 bin shift; warp1: rms
    if (t < 8) {
        float v = red[t];
        #pragma unroll
        for (int o = 4; o > 0; o >>= 1) v += __shfl_xor_sync(0xffu, v, o);
        if (t == 0) {
            float ms = v * (1.0f / (float)D);
            float sigma = sqrtf(ms);                   // |w|~1 heuristic
            float t1 = inv_phi_tail((float)(k + 160) * (0.5f / (float)D));
            float t2 = inv_phi_tail((float)(k - 96 > 1 ? k - 96 : 1) * (0.5f / (float)D));
            unsigned lo = (t1 > 0.0f) ? __float_as_uint(t1 * sigma) : 0u;
            unsigned hq = __float_as_uint(fmaxf(t2, 0.0f) * sigma);
            if (hq <= lo) hq = lo + 1u;
            unsigned wsoft = hq - lo;
            lo_sh = lo;
            s_sh  = (wsoft > (unsigned)BINS) ? (25 - __clz(wsoft - 1u)) : 0;
        }
    }
    if (wid == 1 && lane < 8) {
        float v = red[lane];
        #pragma unroll
        for (int o = 4; o > 0; o >>= 1) v += __shfl_xor_sync(0xffu, v, o);
        if (lane == 0) rms_sh = rsqrtf(v * (1.0f / (float)D) + 1e-6f);
    }
    __syncthreads();                                   // B2

    // ---- phase 1: per-warp candidate compaction (no atomics) ----
    const unsigned lo = lo_sh;
    unsigned* seg = &cand[wid * SEG];
    unsigned nloc = 0u;
    #pragma unroll
    for (int i = 0; i < 8; i++) {
        unsigned ub = __float_as_uint(xw[i]) & 0x7FFFFFFFu;
        bool c = (ub >= lo);
        unsigned m = __ballot_sync(0xffffffffu, c);
        if (c) seg[nloc + __popc(m & ((1u << lane) - 1u))] = ub;
        nloc += (unsigned)__popc(m);
    }
    if (lane == 0) ncw[wid] = nloc;
    __syncthreads();                                   // B3

    // total candidate count (uniform per-thread sum of 8 broadcasts)
    int nc = 0;
    #pragma unroll
    for (int j = 0; j < 8; j++) nc += (int)ncw[j];

    if (nc < k) {   // rare fallback: append the complement -> full set
        #pragma unroll
        for (int i = 0; i < 8; i++) {
            unsigned ub = __float_as_uint(xw[i]) & 0x7FFFFFFFu;
            bool c = (ub < lo);
            unsigned m = __ballot_sync(0xffffffffu, c);
            if (c) seg[nloc + __popc(m & ((1u << lane) - 1u))] = ub;
            nloc += (unsigned)__popc(m);
        }
        if (lane == 0) ncw[wid] = nloc;
        if (t == 0) fb_sh = 1;
        __syncthreads();
    }

    // ---- phase 2: warp0 exact select over candidates (warp-local) ----
    if (wid == 0) {
        unsigned lo2 = fb_sh ? 0u : lo;
        unsigned hi2 = 0x80000000u;
        int s2 = fb_sh ? 24 : s_sh;
        int r = k;
        unsigned cnts[8];
        #pragma unroll
        for (int j = 0; j < 8; j++) cnts[j] = ncw[j];

        while (true) {
            const unsigned range = hi2 - lo2;
            #pragma unroll
            for (int j = 0; j < BINS / 32; j++) hist[lane + 32 * j] = 0u;
            __syncwarp();
            #pragma unroll 1
            for (int sg = 0; sg < 8; sg++) {
                const unsigned* cs = &cand[sg * SEG];
                const int n = (int)cnts[sg];
                for (int i = lane; i < n; i += 32) {
                    unsigned d = cs[i] - lo2;
                    if (d < range) {
                        unsigned b = d >> s2;
                        if (b > (unsigned)(BINS - 1)) b = BINS - 1;
                        atomicAdd(&hist[b], 1u);
                    }
                }
            }
            __syncwarp();

            uint4 hv = *reinterpret_cast<const uint4*>(&hist[lane * 4]);
            unsigned hr[4] = {hv.x, hv.y, hv.z, hv.w};
            unsigned bsum = hr[0] + hr[1] + hr[2] + hr[3];
            unsigned S = bsum;
            #pragma unroll
            for (int o = 1; o < 32; o <<= 1) {
                unsigned v = __shfl_down_sync(0xffffffffu, S, o);
                if (lane + o < 32) S += v;
            }
            unsigned suf = S - bsum;
            int bj = -1; unsigned cb = 0, abv = 0;
            #pragma unroll
            for (int j = 3; j >= 0; j--) {
                unsigned ns = suf + hr[j];
                if (suf < (unsigned)r && ns >= (unsigned)r) { bj = j; cb = hr[j]; abv = suf; }
                suf = ns;
            }
            unsigned bal = __ballot_sync(0xffffffffu, bj >= 0);
            int src = __ffs(bal) - 1;
            unsigned B = __shfl_sync(0xffffffffu, (unsigned)(lane * 4 + bj), src);
            cb  = __shfl_sync(0xffffffffu, cb, src);
            abv = __shfl_sync(0xffffffffu, abv, src);
            int r2 = r - (int)abv;
            unsigned nlo = lo2 + (B << s2);
            unsigned nhi = (B >= (unsigned)(BINS - 1)) ? hi2 : (lo2 + ((B + 1u) << s2));
            if (nhi > hi2) nhi = hi2;

            // bucket min/max by rescanning candidates (<= ~14/lane)
            unsigned bmin = 0xFFFFFFFFu, bmax = 0u;
            const unsigned brange = nhi - nlo;
            #pragma unroll 1
            for (int sg = 0; sg < 8; sg++) {
                const unsigned* cs = &cand[sg * SEG];
                const int n = (int)cnts[sg];
                for (int i = lane; i < n; i += 32) {
                    unsigned ub = cs[i];
                    if (ub - nlo < brange) { bmin = min(bmin, ub); bmax = max(bmax, ub); }
                }
            }
            bmin = __reduce_min_sync(0xffffffffu, bmin);
            bmax = __reduce_max_sync(0xffffffffu, bmax);

            if ((int)cb == r2) { if (lane == 0) thr_sh = bmin; break; }
            if (r2 == 1)       { if (lane == 0) thr_sh = bmax; break; }
            if (bmin == bmax)  { if (lane == 0) thr_sh = bmin; break; }

            lo2 = bmin; hi2 = bmax + 1u;
            unsigned wd = hi2 - lo2;
            s2 = (wd > (unsigned)BINS) ? (25 - __clz(wd - 1u)) : 0;
            r = r2;
        }
    }
    __syncthreads();                                   // B4

    // ---- epilogue: recover xv from smem; out = x + (xw*rms)*g ----
    const float4* gv = reinterpret_cast<const float4*>(g);
    float4 ga = gv[t], gb = gv[t + T];
    float4 sxa = *reinterpret_cast<const float4*>(&xstash[4 * t]);
    float4 sxb = *reinterpret_cast<const float4*>(&xstash[4 * (t + T)]);
    float gf[8] = {ga.x,ga.y,ga.z,ga.w,gb.x,gb.y,gb.z,gb.w};
    float xv[8] = {sxa.x,sxa.y,sxa.z,sxa.w,sxb.x,sxb.y,sxb.z,sxb.w};
    const float rms  = rms_sh;
    const float thrf = __uint_as_float(thr_sh);

    float fo[8];
    #pragma unroll
    for (int i = 0; i < 8; i++) {
        float keep = (fabsf(xw[i]) >= thrf) ? (rms * gf[i]) : 0.0f;
        fo[i] = fmaf(xw[i], keep, xv[i]);
    }
    float4* orow = reinterpret_cast<float4*>(out) + (size_t)row * (D / 4);
    __stcs(orow + t,     make_float4(fo[0], fo[1], fo[2], fo[3]));
    __stcs(orow + t + T, make_float4(fo[4], fo[5], fo[6], fo[7]));
}

extern "C" void kernel_launch(void* const* d_in, const int* in_sizes, int n_in,
                              void* d_out, int out_size)
{
    const float* x = (const float*)d_in[0];
    const float* w = (const float*)d_in[1];
    const float* g = (const float*)d_in[2];
    const int*   k = (const int*)d_in[3];

    int N = in_sizes[0] / D;   // 32768 rows
    sparse_topk_kernel<<<N, T>>>(x, w, g, k, (float*)d_out);
}

// round 15
// speedup vs baseline: 2.6401x; 2.6401x over previous
#include <cuda_runtime.h>

// SparseTopKLayer: out = x + ((x*rms)*w)*mask*gamma
//   rms = rsqrt(mean(x^2)+1e-6); mask = |x_norm| >= kth_largest(|x_norm|, k)
// Rank on |x*w| (rms>0 row-constant -> identical ordering).
// One CTA per row, 256 threads, 8 elems/thread; xv parked in smem (regs=32).
// 256-bin adaptive-window select. Mode-2 exits (bucket fully in top-k) use
// thr = bucket lower bound (provably identical mask) -> no block rescan.
// Exact for arbitrary data via re-windowing.

constexpr int D    = 2048;
constexpr int T    = 256;
constexpr int BINS = 256;

__device__ __forceinline__ float inv_phi_tail(float q) {
    // Phi^{-1}(1-q), q in (0,0.5]; Abramowitz-Stegun 26.2.23, |err|<4.5e-4
    q = fminf(fmaxf(q, 1e-7f), 0.4999f);
    float s = sqrtf(-2.0f * __logf(q));
    return s - (2.30753f + 0.27061f * s) / (1.0f + s * (0.99229f + 0.04481f * s));
}

__global__ void __launch_bounds__(T, 7) sparse_topk_kernel(
    const float* __restrict__ x,
    const float* __restrict__ w,
    const float* __restrict__ g,
    const int* __restrict__ kptr,
    float* __restrict__ out)
{
    const int row  = blockIdx.x;
    const int t    = threadIdx.x;
    const int lane = t & 31;
    const int wid  = t >> 5;

    __shared__ float    red[8];
    __shared__ __align__(16) unsigned hist[2][BINS];
    __shared__ unsigned lo_sh, hi_sh, thr_sh, thrmax_sh;
    __shared__ int      r_sh, s_sh, mode_sh;
    __shared__ float    rms_sh;
    __shared__ __align__(16) float xstash[D];   // xv parked during select

    // ---- load x (streaming), w; xw in regs; xv -> smem; sum x^2 ----
    const float4* xr = reinterpret_cast<const float4*>(x) + (size_t)row * (D / 4);
    const float4* wv = reinterpret_cast<const float4*>(w);
    float4 xa = __ldcs(xr + t), xb = __ldcs(xr + t + T);
    float4 wa = wv[t], wb = wv[t + T];

    float xw[8];
    float ss = 0.0f;
    {
        float xv[8] = {xa.x,xa.y,xa.z,xa.w,xb.x,xb.y,xb.z,xb.w};
        float wf[8] = {wa.x,wa.y,wa.z,wa.w,wb.x,wb.y,wb.z,wb.w};
        #pragma unroll
        for (int i = 0; i < 8; i++) {
            xw[i] = xv[i] * wf[i];
            ss = fmaf(xv[i], xv[i], ss);
        }
        *reinterpret_cast<float4*>(&xstash[4 * t])       = xa;
        *reinterpret_cast<float4*>(&xstash[4 * (t + T)]) = xb;
    }
    #pragma unroll
    for (int o = 16; o > 0; o >>= 1)
        ss += __shfl_xor_sync(0xffffffffu, ss, o);
    if (lane == 0) red[wid] = ss;
    ((unsigned*)hist)[t]       = 0u;           // zero both buffers
    ((unsigned*)hist)[t + 256] = 0u;
    if (t == 0) thrmax_sh = 0u;
    __syncthreads();

    // ---- warp0: rms + quantile window (open top) ----
    if (t < 8) {
        float v = red[t];
        #pragma unroll
        for (int o = 4; o > 0; o >>= 1) v += __shfl_xor_sync(0xffu, v, o);
        if (t == 0) {
            float ms = v * (1.0f / (float)D);
            rms_sh = rsqrtf(ms + 1e-6f);
            float sigma = sqrtf(ms);            // |w|~1 heuristic (window only)
            int k = *kptr;
            float t1 = inv_phi_tail((float)(k + 64) * (0.5f / (float)D));
            float t2 = inv_phi_tail((float)(k - 64 > 1 ? k - 64 : 1) * (0.5f / (float)D));
            unsigned lo = (t1 > 0.0f) ? __float_as_uint(t1 * sigma) : 0u;
            unsigned hq = __float_as_uint(fmaxf(t2, 0.0f) * sigma);
            if (hq <= lo) hq = lo + 1u;
            unsigned wsoft = hq - lo;
            lo_sh = lo;
            hi_sh = 0x80000000u;                // open top: tail folds into bin 255
            s_sh  = (wsoft > (unsigned)BINS) ? (24 - __clz(wsoft - 1u)) : 0;
            r_sh  = k; mode_sh = 0;
        }
    }
    __syncthreads();

    // ---- adaptive-window histogram select (exact) ----
    unsigned thr = 0u;
    int p = 0;
    while (true) {
        const unsigned lo = lo_sh, hi = hi_sh;
        const unsigned range = hi - lo;
        const int s = s_sh;
        unsigned* h = hist[p];
        #pragma unroll
        for (int i = 0; i < 8; i++) {
            unsigned ub = __float_as_uint(xw[i]) & 0x7FFFFFFFu;
            unsigned d = ub - lo;
            if (d < range) {
                unsigned b = d >> s;
                if (b > (unsigned)(BINS - 1)) b = BINS - 1;    // tail bin
                atomicAdd(&h[b], 1u);
            }
        }
        hist[p ^ 1][t] = 0u;                    // prep next buffer (T==BINS)
        __syncthreads();

        if (t < 32) {   // warp0: 8-bin/lane suffix scan + classify + publish
            uint4 h0 = *reinterpret_cast<const uint4*>(&h[lane * 8]);
            uint4 h1 = *reinterpret_cast<const uint4*>(&h[lane * 8 + 4]);
            unsigned hr[8] = {h0.x,h0.y,h0.z,h0.w,h1.x,h1.y,h1.z,h1.w};
            unsigned bsum = 0;
            #pragma unroll
            for (int j = 0; j < 8; j++) bsum += hr[j];
            unsigned S = bsum;
            #pragma unroll
            for (int o = 1; o < 32; o <<= 1) {
                unsigned v = __shfl_down_sync(0xffffffffu, S, o);
                if (lane + o < 32) S += v;
            }
            unsigned total = __shfl_sync(0xffffffffu, S, 0);
            int r = r_sh;

            if ((unsigned)r > total) {           // threshold below window
                if (lane == 0) {
                    unsigned nrange = lo;        // new window [0, lo)
                    hi_sh = lo; lo_sh = 0u;
                    s_sh = (nrange > (unsigned)BINS) ? (24 - __clz(nrange - 1u)) : 0;
                    r_sh = r - (int)total; mode_sh = 0;
                }
            } else {
                unsigned suf = S - bsum;         // count in strictly-higher lanes
                int bj = -1; unsigned cb = 0, abv = 0;
                #pragma unroll
                for (int j = 7; j >= 0; j--) {
                    unsigned ns = suf + hr[j];
                    if (suf < (unsigned)r && ns >= (unsigned)r) { bj = j; cb = hr[j]; abv = suf; }
                    suf = ns;
                }
                unsigned bal = __ballot_sync(0xffffffffu, bj >= 0);
                int src = __ffs(bal) - 1;
                unsigned B = __shfl_sync(0xffffffffu, (unsigned)(lane * 8 + bj), src);
                cb  = __shfl_sync(0xffffffffu, cb, src);
                abv = __shfl_sync(0xffffffffu, abv, src);
                if (lane == 0) {
                    int r2 = r - (int)abv;
                    unsigned nlo = lo + (B << s);
                    unsigned nhi = (B >= (unsigned)(BINS - 1)) ? hi : (lo + ((B + 1u) << s));
                    if (nhi > hi) nhi = hi;
                    unsigned nrange = nhi - nlo;
                    // mode-2 (cnt==r2): whole bucket in top-k -> k-th value is
                    // bucket min; no data lies in [nlo, bmin) so thr=nlo gives
                    // the identical mask. Free exit.
                    if (nrange <= 1u || (int)cb == r2) { mode_sh = 1; thr_sh = nlo; }
                    else if (r2 == 1) { mode_sh = 3; lo_sh = nlo; hi_sh = nhi; }
                    else {
                        lo_sh = nlo; hi_sh = nhi; r_sh = r2; mode_sh = 0;
                        s_sh = (nrange > (unsigned)BINS) ? (24 - __clz(nrange - 1u)) : 0;
                    }
                }
            }
        }
        __syncthreads();

        int m = mode_sh;
        if (m == 1) { thr = thr_sh; break; }
        if (m == 3) {
            // thr = max of bucket candidates (k-th value is the bucket max)
            const unsigned nlo = lo_sh, nrange = hi_sh - lo_sh;
            unsigned lm = 0u;
            #pragma unroll
            for (int i = 0; i < 8; i++) {
                unsigned ub = __float_as_uint(xw[i]) & 0x7FFFFFFFu;
                if (ub - nlo < nrange) lm = max(lm, ub);
            }
            lm = __reduce_max_sync(0xffffffffu, lm);
            if (lane == 0) atomicMax(&thrmax_sh, lm);
            __syncthreads();
            thr = thrmax_sh;
            break;
        }
        p ^= 1;
    }

    // ---- epilogue: recover xv from smem; out = x + (xw*rms)*g ----
    const float4* gv = reinterpret_cast<const float4*>(g);
    float4 ga = gv[t], gb = gv[t + T];
    float4 sxa = *reinterpret_cast<const float4*>(&xstash[4 * t]);
    float4 sxb = *reinterpret_cast<const float4*>(&xstash[4 * (t + T)]);
    float gf[8] = {ga.x,ga.y,ga.z,ga.w,gb.x,gb.y,gb.z,gb.w};
    float xv[8] = {sxa.x,sxa.y,sxa.z,sxa.w,sxb.x,sxb.y,sxb.z,sxb.w};
    const float rms  = rms_sh;
    const float thrf = __uint_as_float(thr);

    float fo[8];
    #pragma unroll
    for (int i = 0; i < 8; i++) {
        float keep = (fabsf(xw[i]) >= thrf) ? (rms * gf[i]) : 0.0f;
        fo[i] = fmaf(xw[i], keep, xv[i]);
    }
    float4* orow = reinterpret_cast<float4*>(out) + (size_t)row * (D / 4);
    __stcs(orow + t,     make_float4(fo[0], fo[1], fo[2], fo[3]));
    __stcs(orow + t + T, make_float4(fo[4], fo[5], fo[6], fo[7]));
}

extern "C" void kernel_launch(void* const* d_in, const int* in_sizes, int n_in,
                              void* d_out, int out_size)
{
    const float* x = (const float*)d_in[0];
    const float* w = (const float*)d_in[1];
    const float* g = (const float*)d_in[2];
    const int*   k = (const int*)d_in[3];

    int N = in_sizes[0] / D;   // 32768 rows
    sparse_topk_kernel<<<N, T>>>(x, w, g, k, (float*)d_out);
}